// round 12
// baseline (speedup 1.0000x reference)
#include <cuda_runtime.h>
#include <cstdint>

// SpikeFP64ScaleBy2K — soft-logic FP64 scale-by-2^k collapsed to integer bit ops.
// R11: champion body (R4: RPW=4, MLP=8, 32 regs, DRAM 86%) with the single
// remaining untested isolated axis: block size 256 -> 512 (WARPS_PER_BLOCK 16).
// Probes CTA->SM placement / L2-die stream locality. Decode chain byte-identical
// to the verified champion (rel_err 0 across R1-R10).

static constexpr int ROWS_PER_WARP = 4;
static constexpr int WARPS_PER_BLOCK = 16;
static constexpr int BLOCK_THREADS = WARPS_PER_BLOCK * 32;

__global__ void __launch_bounds__(BLOCK_THREADS)
scale2k_kernel(const uint2* __restrict__ x2,
               const uint2* __restrict__ k2,
               uint2* __restrict__ o2,
               int nrows)
{
    const int lane = threadIdx.x & 31;
    const int warp = blockIdx.x * WARPS_PER_BLOCK + (threadIdx.x >> 5);
    const int row0 = warp * ROWS_PER_WARP;
    if (row0 >= nrows) return;  // warp-uniform exit

    // ---- per-lane weights (hoisted; lane j holds bit positions 2j, 2j+1) ----
    const unsigned wE_x = (lane >= 1 && lane <= 5) ? (1u << (11 - 2 * lane)) : 0u;
    const unsigned wE_y = (lane <= 5) ? (1u << (10 - 2 * lane)) : 0u;
    const unsigned wV_x = (lane >= 6 && lane <= 13) ? (1u << (26 - 2 * lane)) : 0u;
    const unsigned wV_y = (lane >= 6 && lane <= 12) ? (1u << (25 - 2 * lane)) : 0u;
    const unsigned w1x = (wE_x << 16) | wV_x;
    const unsigned w1y = (wE_y << 16) | wV_y;
    const unsigned w2kx = (lane == 0) ? (1u << 20) : (1u << 12);
    const unsigned w2ky = 1u << 12;
    const unsigned sh_x = (unsigned)(11 - 2 * lane) & 31u;
    const unsigned sh_y = (unsigned)(10 - 2 * lane) & 31u;
    const bool lane_le5 = (lane <= 5);
    const bool lane_ge1 = (lane >= 1);

    // ---- front-batch loads: 8 independent LDG.64 per lane (MLP 8) ----
    uint2 xv[ROWS_PER_WARP];
    uint2 kv[ROWS_PER_WARP];
#pragma unroll
    for (int r = 0; r < ROWS_PER_WARP; ++r) {
        if (row0 + r < nrows) {  // warp-uniform
            const long idx = (long)(row0 + r) * 32 + lane;
            xv[r] = __ldg(&x2[idx]);
            kv[r] = __ldg(&k2[idx]);
        }
    }

#pragma unroll
    for (int r = 0; r < ROWS_PER_WARP; ++r) {
        if (row0 + r >= nrows) break;  // warp-uniform

        // Inputs are exactly 0.0f / 1.0f: bit = bits >> 29.
        const unsigned bkx = kv[r].x >> 29;
        const unsigned bky = kv[r].y >> 29;
        const unsigned bxx = xv[r].x >> 29;
        const unsigned bxy = xv[r].y >> 29;

        const unsigned c1 = bkx * w1x + bky * w1y;
        const unsigned c2 = bxx * wE_x + bxy * wE_y + bkx * w2kx + bky * w2ky;

        const unsigned r1 = __reduce_add_sync(0xFFFFFFFFu, c1);
        const unsigned r2 = __reduce_add_sync(0xFFFFFFFFu, c2);

        // ---- uniform scalar chain (bit-exact, rel_err 0 across all rounds) ----
        const unsigned e_k   = r1 >> 16;
        const unsigned val   = 0x8000u | (r1 & 0xFFFFu);
        const unsigned t     = (~(e_k + 1025u)) & 15u;
        const unsigned k_abs = (val >> t) & 0x7FFu;
        const unsigned s_k   = (r2 >> 20) & 1u;
        const unsigned k_fin = s_k ? ((0u - k_abs) & 0x7FFu) : k_abs;
        const unsigned e_x   = r2 & 0x7FFu;
        const unsigned e_new = (e_x + k_fin) & 0x7FFu;
        const bool nz        = ((r2 >> 12) & 0xFFu) != 0u;

        // ---- patch exponent field (bits 1..11 -> lanes 0..5), branch-free ----
        const unsigned px = ((e_new >> sh_x) & 1u) * 0x3F800000u;
        const unsigned py = ((e_new >> sh_y) & 1u) * 0x3F800000u;

        uint2 ov = xv[r];
        const bool patch = nz && lane_le5;
        ov.x = (patch && lane_ge1) ? px : ov.x;
        ov.y = patch ? py : ov.y;

        const long idx = (long)(row0 + r) * 32 + lane;
        o2[idx] = ov;
    }
}

extern "C" void kernel_launch(void* const* d_in, const int* in_sizes, int n_in,
                              void* d_out, int out_size) {
    const uint2* x2 = (const uint2*)d_in[0];
    const uint2* k2 = (const uint2*)d_in[1];
    uint2* o2 = (uint2*)d_out;

    const int nrows = in_sizes[0] / 64;
    const int nwarps = (nrows + ROWS_PER_WARP - 1) / ROWS_PER_WARP;
    const int nblocks = (nwarps + WARPS_PER_BLOCK - 1) / WARPS_PER_BLOCK;

    scale2k_kernel<<<nblocks, BLOCK_THREADS>>>(x2, k2, o2, nrows);
}

// round 13
// speedup vs baseline: 1.0005x; 1.0005x over previous
#include <cuda_runtime.h>
#include <cstdint>

// SpikeFP64ScaleBy2K — soft-logic FP64 scale-by-2^k collapsed to integer bit ops.
// FINAL champion: 115.2us timed / ~112.5us kernel, DRAM ~86%, 6.85 TB/s —
// at the measured mixed-stream (2R:1W) HBM ceiling of sm_103a.
//
// Reference semantics (decoded from the gate network; bit-exact, rel_err 0.0
// in every round): rows of 64 float "bits" (0.0/1.0), MSB-first IEEE-754
// double layout. Output = x with its 11-bit exponent field replaced by
// e_x + trunc(k) (mod 2048), unless bits 1..63 of k are all zero (then copy x).
//
// Design — every element validated by an isolated experiment (12 rounds):
//   - warp-per-row: lane j holds bits {2j,2j+1} via one coalesced LDG.64
//   - ROWS_PER_WARP=4 -> 8 front-batched loads (MLP=8): measured optimum of
//     the occ x MLP curve (MLP4: 118.4us, MLP8: 115.2us, MLP16: 119.5us;
//     persistent-grid variant that broke front-batching: 176.6us)
//   - bit extract: inputs are exactly 0.0f/1.0f -> bit = bits>>29 (single SHF)
//   - field decode: 2x __reduce_add_sync (REDUX.ADD) of packed per-lane weights
//       r1 = sum((e_k_w<<16)|val_w): e_k = r1>>16, top-15 mantissa = r1&0x7FFF
//       r2 = sum(e_x_w | nz<<12 | sign<<20)
//     (replaced ballot+Morton decode: ALU pipe 84% -> 64%)
//   - uniform scalar chain: t = ~(e_k+1025)&15; k_abs = (0x8000|frac)>>t & 0x7FF;
//     two's-complement negate if s_k; e_new = (e_x + k_final) & 0x7FF
//   - patch exponent bits 1..11 (lanes 0..5) branch-free via *0x3F800000 (no I2F)
//   - full-grid launch, block 256, default cache policy, 32 regs, occ ~82%

static constexpr int ROWS_PER_WARP = 4;
static constexpr int WARPS_PER_BLOCK = 8;
static constexpr int BLOCK_THREADS = WARPS_PER_BLOCK * 32;

__global__ void __launch_bounds__(BLOCK_THREADS)
scale2k_kernel(const uint2* __restrict__ x2,
               const uint2* __restrict__ k2,
               uint2* __restrict__ o2,
               int nrows)
{
    const int lane = threadIdx.x & 31;
    const int warp = blockIdx.x * WARPS_PER_BLOCK + (threadIdx.x >> 5);
    const int row0 = warp * ROWS_PER_WARP;
    if (row0 >= nrows) return;  // warp-uniform exit

    // ---- per-lane weights (hoisted; lane j holds bit positions 2j, 2j+1) ----
    const unsigned wE_x = (lane >= 1 && lane <= 5) ? (1u << (11 - 2 * lane)) : 0u;
    const unsigned wE_y = (lane <= 5) ? (1u << (10 - 2 * lane)) : 0u;
    const unsigned wV_x = (lane >= 6 && lane <= 13) ? (1u << (26 - 2 * lane)) : 0u;
    const unsigned wV_y = (lane >= 6 && lane <= 12) ? (1u << (25 - 2 * lane)) : 0u;
    const unsigned w1x = (wE_x << 16) | wV_x;
    const unsigned w1y = (wE_y << 16) | wV_y;
    const unsigned w2kx = (lane == 0) ? (1u << 20) : (1u << 12);
    const unsigned w2ky = 1u << 12;
    const unsigned sh_x = (unsigned)(11 - 2 * lane) & 31u;
    const unsigned sh_y = (unsigned)(10 - 2 * lane) & 31u;
    const bool lane_le5 = (lane <= 5);
    const bool lane_ge1 = (lane >= 1);

    // ---- front-batch loads: 8 independent LDG.64 per lane (MLP 8) ----
    uint2 xv[ROWS_PER_WARP];
    uint2 kv[ROWS_PER_WARP];
#pragma unroll
    for (int r = 0; r < ROWS_PER_WARP; ++r) {
        if (row0 + r < nrows) {  // warp-uniform
            const long idx = (long)(row0 + r) * 32 + lane;
            xv[r] = __ldg(&x2[idx]);
            kv[r] = __ldg(&k2[idx]);
        }
    }

#pragma unroll
    for (int r = 0; r < ROWS_PER_WARP; ++r) {
        if (row0 + r >= nrows) break;  // warp-uniform

        // Inputs are exactly 0.0f / 1.0f: bit = bits >> 29.
        const unsigned bkx = kv[r].x >> 29;
        const unsigned bky = kv[r].y >> 29;
        const unsigned bxx = xv[r].x >> 29;
        const unsigned bxy = xv[r].y >> 29;

        const unsigned c1 = bkx * w1x + bky * w1y;
        const unsigned c2 = bxx * wE_x + bxy * wE_y + bkx * w2kx + bky * w2ky;

        const unsigned r1 = __reduce_add_sync(0xFFFFFFFFu, c1);
        const unsigned r2 = __reduce_add_sync(0xFFFFFFFFu, c2);

        // ---- uniform scalar chain (bit-exact, rel_err 0 across all rounds) ----
        const unsigned e_k   = r1 >> 16;
        const unsigned val   = 0x8000u | (r1 & 0xFFFFu);
        const unsigned t     = (~(e_k + 1025u)) & 15u;
        const unsigned k_abs = (val >> t) & 0x7FFu;
        const unsigned s_k   = (r2 >> 20) & 1u;
        const unsigned k_fin = s_k ? ((0u - k_abs) & 0x7FFu) : k_abs;
        const unsigned e_x   = r2 & 0x7FFu;
        const unsigned e_new = (e_x + k_fin) & 0x7FFu;
        const bool nz        = ((r2 >> 12) & 0xFFu) != 0u;

        // ---- patch exponent field (bits 1..11 -> lanes 0..5), branch-free ----
        const unsigned px = ((e_new >> sh_x) & 1u) * 0x3F800000u;
        const unsigned py = ((e_new >> sh_y) & 1u) * 0x3F800000u;

        uint2 ov = xv[r];
        const bool patch = nz && lane_le5;
        ov.x = (patch && lane_ge1) ? px : ov.x;
        ov.y = patch ? py : ov.y;

        const long idx = (long)(row0 + r) * 32 + lane;
        o2[idx] = ov;
    }
}

extern "C" void kernel_launch(void* const* d_in, const int* in_sizes, int n_in,
                              void* d_out, int out_size) {
    const uint2* x2 = (const uint2*)d_in[0];
    const uint2* k2 = (const uint2*)d_in[1];
    uint2* o2 = (uint2*)d_out;

    const int nrows = in_sizes[0] / 64;
    const int nwarps = (nrows + ROWS_PER_WARP - 1) / ROWS_PER_WARP;
    const int nblocks = (nwarps + WARPS_PER_BLOCK - 1) / WARPS_PER_BLOCK;

    scale2k_kernel<<<nblocks, BLOCK_THREADS>>>(x2, k2, o2, nrows);
}

// round 14
// speedup vs baseline: 1.0088x; 1.0083x over previous
#include <cuda_runtime.h>
#include <cstdint>

// SpikeFP64ScaleBy2K — soft-logic FP64 scale-by-2^k collapsed to integer bit ops.
// R13: champion body (115.2us best, DRAM 86.8%, reproduced 4x) with ONE isolated
// change: __stwt write-through store. Output has zero reuse; WT avoids L2
// dirty-line allocation/writeback interleaving with the two read streams.
// Loads stay plain __ldg (the R7 regression came from the .cs LOAD path's
// register cost; store modifier alone should leave regs at 32).
// Decode chain byte-identical to the verified champion (rel_err 0, R1-R12).

static constexpr int ROWS_PER_WARP = 4;
static constexpr int WARPS_PER_BLOCK = 8;
static constexpr int BLOCK_THREADS = WARPS_PER_BLOCK * 32;

__global__ void __launch_bounds__(BLOCK_THREADS)
scale2k_kernel(const uint2* __restrict__ x2,
               const uint2* __restrict__ k2,
               uint2* __restrict__ o2,
               int nrows)
{
    const int lane = threadIdx.x & 31;
    const int warp = blockIdx.x * WARPS_PER_BLOCK + (threadIdx.x >> 5);
    const int row0 = warp * ROWS_PER_WARP;
    if (row0 >= nrows) return;  // warp-uniform exit

    // ---- per-lane weights (hoisted; lane j holds bit positions 2j, 2j+1) ----
    const unsigned wE_x = (lane >= 1 && lane <= 5) ? (1u << (11 - 2 * lane)) : 0u;
    const unsigned wE_y = (lane <= 5) ? (1u << (10 - 2 * lane)) : 0u;
    const unsigned wV_x = (lane >= 6 && lane <= 13) ? (1u << (26 - 2 * lane)) : 0u;
    const unsigned wV_y = (lane >= 6 && lane <= 12) ? (1u << (25 - 2 * lane)) : 0u;
    const unsigned w1x = (wE_x << 16) | wV_x;
    const unsigned w1y = (wE_y << 16) | wV_y;
    const unsigned w2kx = (lane == 0) ? (1u << 20) : (1u << 12);
    const unsigned w2ky = 1u << 12;
    const unsigned sh_x = (unsigned)(11 - 2 * lane) & 31u;
    const unsigned sh_y = (unsigned)(10 - 2 * lane) & 31u;
    const bool lane_le5 = (lane <= 5);
    const bool lane_ge1 = (lane >= 1);

    // ---- front-batch loads: 8 independent LDG.64 per lane (MLP 8) ----
    uint2 xv[ROWS_PER_WARP];
    uint2 kv[ROWS_PER_WARP];
#pragma unroll
    for (int r = 0; r < ROWS_PER_WARP; ++r) {
        if (row0 + r < nrows) {  // warp-uniform
            const long idx = (long)(row0 + r) * 32 + lane;
            xv[r] = __ldg(&x2[idx]);
            kv[r] = __ldg(&k2[idx]);
        }
    }

#pragma unroll
    for (int r = 0; r < ROWS_PER_WARP; ++r) {
        if (row0 + r >= nrows) break;  // warp-uniform

        // Inputs are exactly 0.0f / 1.0f: bit = bits >> 29.
        const unsigned bkx = kv[r].x >> 29;
        const unsigned bky = kv[r].y >> 29;
        const unsigned bxx = xv[r].x >> 29;
        const unsigned bxy = xv[r].y >> 29;

        const unsigned c1 = bkx * w1x + bky * w1y;
        const unsigned c2 = bxx * wE_x + bxy * wE_y + bkx * w2kx + bky * w2ky;

        const unsigned r1 = __reduce_add_sync(0xFFFFFFFFu, c1);
        const unsigned r2 = __reduce_add_sync(0xFFFFFFFFu, c2);

        // ---- uniform scalar chain (bit-exact, rel_err 0 across all rounds) ----
        const unsigned e_k   = r1 >> 16;
        const unsigned val   = 0x8000u | (r1 & 0xFFFFu);
        const unsigned t     = (~(e_k + 1025u)) & 15u;
        const unsigned k_abs = (val >> t) & 0x7FFu;
        const unsigned s_k   = (r2 >> 20) & 1u;
        const unsigned k_fin = s_k ? ((0u - k_abs) & 0x7FFu) : k_abs;
        const unsigned e_x   = r2 & 0x7FFu;
        const unsigned e_new = (e_x + k_fin) & 0x7FFu;
        const bool nz        = ((r2 >> 12) & 0xFFu) != 0u;

        // ---- patch exponent field (bits 1..11 -> lanes 0..5), branch-free ----
        const unsigned px = ((e_new >> sh_x) & 1u) * 0x3F800000u;
        const unsigned py = ((e_new >> sh_y) & 1u) * 0x3F800000u;

        uint2 ov = xv[r];
        const bool patch = nz && lane_le5;
        ov.x = (patch && lane_ge1) ? px : ov.x;
        ov.y = patch ? py : ov.y;

        const long idx = (long)(row0 + r) * 32 + lane;
        __stwt(&o2[idx], ov);           // write-through: no L2 dirty allocation
    }
}

extern "C" void kernel_launch(void* const* d_in, const int* in_sizes, int n_in,
                              void* d_out, int out_size) {
    const uint2* x2 = (const uint2*)d_in[0];
    const uint2* k2 = (const uint2*)d_in[1];
    uint2* o2 = (uint2*)d_out;

    const int nrows = in_sizes[0] / 64;
    const int nwarps = (nrows + ROWS_PER_WARP - 1) / ROWS_PER_WARP;
    const int nblocks = (nwarps + WARPS_PER_BLOCK - 1) / WARPS_PER_BLOCK;

    scale2k_kernel<<<nblocks, BLOCK_THREADS>>>(x2, k2, o2, nrows);
}